// round 2
// baseline (speedup 1.0000x reference)
#include <cuda_runtime.h>
#include <cstdint>

// CC3DTrack: per-track Kalman update + embedding EMA.
// Inputs (metadata order):
//  0 boxes_3d        (N,12)  f32
//  1 obs_boxes_3d    (N,7)   f32
//  2 prev_boxes7     (N,7)   f32
//  3 prev_means      (N,10)  f32
//  4 prev_covs       (N,100) f32
//  5 prev_velocities (N,7)   f32
//  6 prev_embeddings (N,256) f32
//  7 embeddings      (N,256) f32
//  8 acc_frames      (N,)    i32
//  9 frame_gap       (N,)    i32
// 10 matched         (N,)    bool -> marshalled as int32 (harness supports f32/i32/bf16 only)
// 11 fps             scalar
//
// Output (concatenated f32): boxes(12N) | means(10N) | covs(100N) | vel(7N) | emb(256N) | acc(1N)

#define MD 7
#define SD 10

__global__ __launch_bounds__(128)
void kf_kernel(const float* __restrict__ boxes,
               const float* __restrict__ obs,
               const float* __restrict__ prev_b7,
               const float* __restrict__ prev_mean,
               const float* __restrict__ prev_cov,
               const float* __restrict__ prev_vel,
               const int*   __restrict__ acc_frames,
               const int*   __restrict__ frame_gap,
               const int*   __restrict__ matched,
               const int*   __restrict__ fps_p,
               float* __restrict__ out, int N)
{
    int n = blockIdx.x * blockDim.x + threadIdx.x;
    if (n >= N) return;

    // fps may be serialized as int32 or float32; sniff the bits.
    int fbits = fps_p[0];
    float fps = ((unsigned)fbits < 1000000u) ? (float)fbits : __int_as_float(fbits);

    const float* C = prev_cov + (size_t)n * 100;
    const bool mt = matched[n] != 0;

    // ---- Cholesky of S = C[0:7,0:7] + I (SPD by construction) ----
    float L[MD][MD];
    float dinv[MD];
    #pragma unroll
    for (int i = 0; i < MD; i++) {
        #pragma unroll
        for (int j = 0; j <= i; j++) {
            float s = C[i * SD + j] + (i == j ? 1.0f : 0.0f);
            #pragma unroll
            for (int k = 0; k < j; k++) s -= L[i][k] * L[j][k];
            if (j == i) {
                float d = sqrtf(s);
                L[i][i] = d;
                dinv[i] = 1.0f / d;
            } else {
                L[i][j] = s * dinv[j];
            }
        }
    }

    // ---- W[j][:] = L^{-1} * PHt[j,:]^T  (PHt[j,k] = C[j,k], k<7), j = 0..9 ----
    // Then: (K S K^T)[i][j] = W_i . W_j   and   (K innov)[j] = W_j . (L^{-1} innov)
    float W[SD][MD];
    #pragma unroll
    for (int j = 0; j < SD; j++) {
        float p[MD];
        #pragma unroll
        for (int k = 0; k < MD; k++) p[k] = C[j * SD + k];
        #pragma unroll
        for (int k = 0; k < MD; k++) {
            float s = p[k];
            #pragma unroll
            for (int m = 0; m < k; m++) s -= L[k][m] * W[j][m];
            W[j][k] = s * dinv[k];
        }
    }

    // ---- mean update ----
    float m[SD], o7[MD];
    {
        const float* pm = prev_mean + (size_t)n * SD;
        #pragma unroll
        for (int j = 0; j < SD; j++) m[j] = pm[j];
        const float* po = obs + (size_t)n * MD;
        #pragma unroll
        for (int k = 0; k < MD; k++) o7[k] = po[k];
    }
    float u[MD];
    #pragma unroll
    for (int k = 0; k < MD; k++) {
        float s = o7[k] - m[k];
        #pragma unroll
        for (int mm = 0; mm < k; mm++) s -= L[k][mm] * u[mm];
        u[k] = s * dinv[k];
    }
    float mu[SD];
    #pragma unroll
    for (int j = 0; j < SD; j++) {
        float d = 0.0f;
        #pragma unroll
        for (int k = 0; k < MD; k++) d += W[j][k] * u[k];
        mu[j] = m[j] + d;
    }

    // ---- new_means ----
    {
        float* om = out + (size_t)N * 12 + (size_t)n * SD;
        float r[SD];
        #pragma unroll
        for (int j = 0; j < MD; j++) r[j] = mt ? mu[j] : o7[j];
        #pragma unroll
        for (int j = MD; j < SD; j++) r[j] = mt ? mu[j] : 0.0f;
        // 10 floats, 8-byte aligned -> 5x float2
        float2* om2 = reinterpret_cast<float2*>(om);
        #pragma unroll
        for (int q = 0; q < 5; q++) om2[q] = make_float2(r[2 * q], r[2 * q + 1]);
    }

    // ---- new_covs: cov_u = C - W W^T (or init diag), 25x float4 stream ----
    {
        const float4* C4 = reinterpret_cast<const float4*>(C);
        float4* oc4 = reinterpret_cast<float4*>(out + (size_t)N * 22 + (size_t)n * 100);
        #pragma unroll
        for (int q4 = 0; q4 < 25; q4++) {
            float4 cv = C4[q4];
            float r[4];
            #pragma unroll
            for (int t = 0; t < 4; t++) {
                int q = q4 * 4 + t;
                int i = q / SD, j = q % SD;
                float c = (t == 0) ? cv.x : (t == 1) ? cv.y : (t == 2) ? cv.z : cv.w;
                float d = 0.0f;
                #pragma unroll
                for (int k = 0; k < MD; k++) d += W[i][k] * W[j][k];
                float cu = c - d;
                float ci = (i == j) ? ((i < MD) ? 10.0f : 10000.0f) : 0.0f;
                r[t] = mt ? cu : ci;
            }
            oc4[q4] = make_float4(r[0], r[1], r[2], r[3]);
        }
    }

    // ---- new_boxes_3d ----
    {
        const float4* B4 = reinterpret_cast<const float4*>(boxes + (size_t)n * 12);
        float4 b0 = B4[0], b1 = B4[1], b2 = B4[2];
        float b[12] = {b0.x, b0.y, b0.z, b0.w, b1.x, b1.y, b1.z, b1.w, b2.x, b2.y, b2.z, b2.w};
        float r[12];
        #pragma unroll
        for (int j = 0; j < 6; j++) r[j] = mt ? mu[j] : b[j];
        r[6] = b[6];
        r[7] = b[7];
        r[8] = mt ? mu[6] : b[8];
        #pragma unroll
        for (int j = 0; j < 3; j++) r[9 + j] = mt ? (mu[MD + j] * fps) : b[9 + j];
        float4* ob4 = reinterpret_cast<float4*>(out + (size_t)n * 12);
        ob4[0] = make_float4(r[0], r[1], r[2], r[3]);
        ob4[1] = make_float4(r[4], r[5], r[6], r[7]);
        ob4[2] = make_float4(r[8], r[9], r[10], r[11]);
    }

    // ---- velocities + acc_frames ----
    {
        float gap = (float)frame_gap[n];
        float acc = (float)acc_frames[n];
        const float* pb = prev_b7 + (size_t)n * MD;
        const float* pv = prev_vel + (size_t)n * MD;
        float* ov = out + (size_t)N * 122 + (size_t)n * MD;
        float inv_gap = 1.0f / gap;
        float inv_acc1 = 1.0f / (acc + 1.0f);
        #pragma unroll
        for (int k = 0; k < MD; k++) {
            float vobs = (mu[k] - pb[k]) * inv_gap;
            float vm = (pv[k] * acc + vobs) * inv_acc1;
            ov[k] = mt ? vm : 0.0f;
        }
        out[(size_t)N * 385 + n] = mt ? (acc + 1.0f) : 0.0f;
    }
}

// Embedding EMA: 64 threads per track (float4), warp-uniform matched branch
// so unmatched tracks never touch prev_embeddings (saves DRAM traffic).
__global__ __launch_bounds__(256)
void emb_kernel(const float4* __restrict__ prev_emb,
                const float4* __restrict__ emb,
                const int* __restrict__ matched,
                float4* __restrict__ out, int total4)
{
    int idx = blockIdx.x * blockDim.x + threadIdx.x;
    if (idx >= total4) return;
    bool mt = matched[idx >> 6] != 0;
    float4 ev = emb[idx];
    float4 r;
    if (mt) {
        float4 pv = prev_emb[idx];
        r.x = 0.2f * pv.x + 0.8f * ev.x;
        r.y = 0.2f * pv.y + 0.8f * ev.y;
        r.z = 0.2f * pv.z + 0.8f * ev.z;
        r.w = 0.2f * pv.w + 0.8f * ev.w;
    } else {
        r = ev;
    }
    out[idx] = r;
}

extern "C" void kernel_launch(void* const* d_in, const int* in_sizes, int n_in,
                              void* d_out, int out_size)
{
    const float* boxes   = (const float*)d_in[0];
    const float* obs     = (const float*)d_in[1];
    const float* prev_b7 = (const float*)d_in[2];
    const float* prev_m  = (const float*)d_in[3];
    const float* prev_c  = (const float*)d_in[4];
    const float* prev_v  = (const float*)d_in[5];
    const float* prev_e  = (const float*)d_in[6];
    const float* emb     = (const float*)d_in[7];
    const int*   acc     = (const int*)d_in[8];
    const int*   gap     = (const int*)d_in[9];
    const int*   matched = (const int*)d_in[10];
    const int*   fps     = (const int*)d_in[11];
    float* out = (float*)d_out;

    int N = in_sizes[8];  // acc_frames element count == N

    int threadsA = 128;
    int blocksA = (N + threadsA - 1) / threadsA;
    kf_kernel<<<blocksA, threadsA>>>(boxes, obs, prev_b7, prev_m, prev_c, prev_v,
                                     acc, gap, matched, fps, out, N);

    int total4 = N * 64;  // N*256 floats / 4
    int threadsB = 256;
    int blocksB = (total4 + threadsB - 1) / threadsB;
    emb_kernel<<<blocksB, threadsB>>>((const float4*)prev_e, (const float4*)emb,
                                      matched,
                                      (float4*)(out + (size_t)N * 129), total4);
}